// round 16
// baseline (speedup 1.0000x reference)
#include <cuda_runtime.h>
#include <cuda_fp16.h>
#include <math.h>
#include <stdint.h>

#define I_DIM 32
#define J_DIM 32
#define S_DIM 256
#define H_DIM 768
#define NTH 256
#define NCHUNK 12          // 768 / 64
#define NSTAGE 3

// smem byte offsets (from 128B-aligned base). Stage = Q 16K + K 16K.
#define STAGE_STRIDE 32768
#define OFF_Q   0
#define OFF_K   16384
#define OFF_DTAB 98304
#define OFF_KM   99328
#define OFF_QM   99840
#define OFF_PSE  100352        // 4 n-warps * 128 rows
#define OFF_PSC  102400
#define SMEM_DYN (104448 + 128)

// ----------------------------------------------------------- device scratch
__device__ __align__(16) __half g_qh[I_DIM * S_DIM * H_DIM];
__device__ __align__(16) __half g_kh[J_DIM * S_DIM * H_DIM];
// per-row unnormalized softmax partials: [(i*32+j)*256 + s_glob]*2 + ntile
__device__ float g_pse[I_DIM * J_DIM * S_DIM * 2];
__device__ float g_psc[I_DIM * J_DIM * S_DIM * 2];

// --------------------------------------------------------------- asm helpers
__device__ __forceinline__ uint32_t smem_u32(const void* p) {
    uint32_t a;
    asm("{ .reg .u64 t; cvta.to.shared.u64 t, %1; cvt.u32.u64 %0, t; }" : "=r"(a) : "l"(p));
    return a;
}
__device__ __forceinline__ void cp16(uint32_t s, const void* g) {
    asm volatile("{ .reg .u64 gg; cvta.to.global.u64 gg, %1; cp.async.cg.shared.global [%0], [gg], 16; }"
                 :: "r"(s), "l"(g));
}
#define CP_COMMIT() asm volatile("cp.async.commit_group;" ::: "memory")
#define CP_WAIT(N)  asm volatile("cp.async.wait_group %0;" :: "n"(N) : "memory")

__device__ __forceinline__ void ldsm4(uint32_t* A, uint32_t addr) {
    asm volatile("ldmatrix.sync.aligned.m8n8.x4.shared.b16 {%0,%1,%2,%3}, [%4];"
                 : "=r"(A[0]), "=r"(A[1]), "=r"(A[2]), "=r"(A[3]) : "r"(addr));
}
__device__ __forceinline__ void mma16816(float* c, const uint32_t* a, uint32_t b0, uint32_t b1) {
    asm volatile("mma.sync.aligned.m16n8k16.row.col.f32.f16.f16.f32 "
                 "{%0,%1,%2,%3}, {%4,%5,%6,%7}, {%8,%9}, {%0,%1,%2,%3};"
                 : "+f"(c[0]), "+f"(c[1]), "+f"(c[2]), "+f"(c[3])
                 : "r"(a[0]), "r"(a[1]), "r"(a[2]), "r"(a[3]), "r"(b0), "r"(b1));
}

// --------------------- normalize -> fp16, TWO rows per warp (MLP 12)
__global__ __launch_bounds__(256, 4)
void norm_kernel(const float* __restrict__ q, const float* __restrict__ k) {
    const int w = threadIdx.x >> 5;
    const int lane = threadIdx.x & 31;
    const int row0 = blockIdx.x * 16 + w;
    const int row1 = row0 + 8;

    const int lc0 = (row0 < I_DIM * S_DIM) ? row0 : row0 - I_DIM * S_DIM;
    const int lc1 = (row1 < I_DIM * S_DIM) ? row1 : row1 - I_DIM * S_DIM;
    const float* x0 = ((row0 < I_DIM * S_DIM) ? q : k) + (size_t)lc0 * H_DIM;
    const float* x1 = ((row1 < I_DIM * S_DIM) ? q : k) + (size_t)lc1 * H_DIM;
    __half* h0 = ((row0 < I_DIM * S_DIM) ? g_qh : g_kh) + (size_t)lc0 * H_DIM;
    __half* h1 = ((row1 < I_DIM * S_DIM) ? g_qh : g_kh) + (size_t)lc1 * H_DIM;

    float4 v0[6], v1[6];
    #pragma unroll
    for (int e = 0; e < 6; e++) v0[e] = *reinterpret_cast<const float4*>(x0 + (lane + e * 32) * 4);
    #pragma unroll
    for (int e = 0; e < 6; e++) v1[e] = *reinterpret_cast<const float4*>(x1 + (lane + e * 32) * 4);

    float s0 = 0.0f, s1 = 0.0f;
    #pragma unroll
    for (int e = 0; e < 6; e++) {
        s0 += v0[e].x * v0[e].x + v0[e].y * v0[e].y + v0[e].z * v0[e].z + v0[e].w * v0[e].w;
        s1 += v1[e].x * v1[e].x + v1[e].y * v1[e].y + v1[e].z * v1[e].z + v1[e].w * v1[e].w;
    }
    #pragma unroll
    for (int o = 16; o; o >>= 1) {
        s0 += __shfl_xor_sync(0xffffffffu, s0, o);
        s1 += __shfl_xor_sync(0xffffffffu, s1, o);
    }
    const float iv0 = 1.0f / fmaxf(sqrtf(s0), 1e-12f);
    const float iv1 = 1.0f / fmaxf(sqrtf(s1), 1e-12f);

    #pragma unroll
    for (int e = 0; e < 6; e++) {
        __half2 a0 = __floats2half2_rn(v0[e].x * iv0, v0[e].y * iv0);
        __half2 b0 = __floats2half2_rn(v0[e].z * iv0, v0[e].w * iv0);
        uint2 w0; w0.x = *reinterpret_cast<uint32_t*>(&a0); w0.y = *reinterpret_cast<uint32_t*>(&b0);
        *reinterpret_cast<uint2*>(h0 + (lane + e * 32) * 4) = w0;
        __half2 a1 = __floats2half2_rn(v1[e].x * iv1, v1[e].y * iv1);
        __half2 b1 = __floats2half2_rn(v1[e].z * iv1, v1[e].w * iv1);
        uint2 w1; w1.x = *reinterpret_cast<uint32_t*>(&a1); w1.y = *reinterpret_cast<uint32_t*>(&b1);
        *reinterpret_cast<uint2*>(h1 + (lane + e * 32) * 4) = w1;
    }
}

// ----------------------------------------------------------- stage loader
// 128 rows x 64 halves (128B = 8 x 16B groups), swizzle: group ^= row&7.
__device__ __forceinline__ void load_stage(uint32_t qdst, uint32_t kdst,
                                           const char* qsrc, const char* ksrc, int tid) {
    #pragma unroll
    for (int it = 0; it < 4; it++) {               // Q: 128 rows
        const int idx = tid + it * NTH;
        const int row = idx >> 3, g = idx & 7, gs = g ^ (row & 7);
        cp16(qdst + row * 128 + gs * 16, qsrc + (size_t)row * 1536 + g * 16);
    }
    #pragma unroll
    for (int it = 0; it < 4; it++) {               // K: 128 rows
        const int idx = tid + it * NTH;
        const int row = idx >> 3, g = idx & 7, gs = g ^ (row & 7);
        cp16(kdst + row * 128 + gs * 16, ksrc + (size_t)row * 1536 + g * 16);
    }
}

// ----------------------------------------------------------- chunk compute
// Warp tiling: 2 m-warps (64 rows) x 4 n-warps (32 cols). acc[mf(4)][nf(4)][4]
// B fragments double-buffered across ks steps.
__device__ __forceinline__ void compute_chunk(
    uint32_t qs, uint32_t ks_, float acc[4][4][4],
    uint32_t arow_off0, uint32_t hb, uint32_t l7,
    uint32_t brow_off, uint32_t bksel)
{
    uint32_t B[2][2][4];
    {
        const uint32_t bg = (bksel ^ l7) << 4;
        ldsm4(B[0][0], ks_ + brow_off + bg);
        ldsm4(B[0][1], ks_ + brow_off + 2048 + bg);
    }
    #pragma unroll
    for (int ks = 0; ks < 4; ks++) {
        const int cur = ks & 1, nxt = cur ^ 1;
        uint32_t A[4][4];
        const uint32_t agrp = (2u * ks + hb) ^ l7;
        #pragma unroll
        for (int mf = 0; mf < 4; mf++)
            ldsm4(A[mf], qs + arow_off0 + mf * 2048 + (agrp << 4));
        if (ks < 3) {
            const uint32_t bgn = ((2u * (ks + 1) + bksel) ^ l7) << 4;
            ldsm4(B[nxt][0], ks_ + brow_off + bgn);
            ldsm4(B[nxt][1], ks_ + brow_off + 2048 + bgn);
        }
        #pragma unroll
        for (int p = 0; p < 2; p++) {
            #pragma unroll
            for (int half = 0; half < 2; half++) {
                const int nf = 2 * p + half;
                const uint32_t b0 = B[cur][p][half * 2], b1 = B[cur][p][half * 2 + 1];
                mma16816(acc[0][nf], A[0], b0, b1);
                mma16816(acc[1][nf], A[1], b0, b1);
                mma16816(acc[2][nf], A[2], b0, b1);
                mma16816(acc[3][nf], A[3], b0, b1);
            }
        }
    }
}

// ------------------------------------------------ fused pair GEMM + partials
__global__ __launch_bounds__(NTH, 2)
void pair_kernel(const float* __restrict__ q_mask, const float* __restrict__ k_mask,
                 const float* __restrict__ alpha_raw)
{
    extern __shared__ char smraw[];
    const uint32_t rawu = smem_u32(smraw);
    const uint32_t pad = (128u - (rawu & 127u)) & 127u;
    char* sb = smraw + pad;
    const uint32_t sbu = rawu + pad;

    const int mtile = blockIdx.x & 1;
    const int ntile = blockIdx.x >> 1;
    const int j = blockIdx.y;
    const int i = blockIdx.z;
    const int tid = threadIdx.x;
    const int wid = tid >> 5;
    const int lane = tid & 31;
    const int warp_m = wid & 1;        // 2 m-warps (64 s-rows each)
    const int warp_n = wid >> 1;       // 4 n-warps (32 t-cols each)
    const uint32_t gid = lane >> 2, tig = lane & 3;
    const uint32_t hb = lane >> 4, l7 = lane & 7;

    float* dtab = (float*)(sb + OFF_DTAB);
    float* km_s = (float*)(sb + OFF_KM);
    float* qm_s = (float*)(sb + OFF_QM);
    float* pse  = (float*)(sb + OFF_PSE);
    float* psc  = (float*)(sb + OFF_PSC);

    const float araw  = __ldg(alpha_raw);
    const float alpha = fmaxf(araw, 0.0f) + log1pf(expf(-fabsf(araw)));
    dtab[tid] = expf(-alpha * (float)tid);
    if (tid < 128) {
        km_s[tid] = k_mask[j * S_DIM + ntile * 128 + tid];
        qm_s[tid] = q_mask[i * S_DIM + mtile * 128 + tid];
    }

    const char* qsrc = (const char*)(g_qh + ((size_t)i * S_DIM + mtile * 128) * H_DIM);
    const char* ksrc = (const char*)(g_kh + ((size_t)j * S_DIM + ntile * 128) * H_DIM);

    // prologue: chunks 0,1 into stages 0,1
    #pragma unroll
    for (int c = 0; c < 2; c++) {
        load_stage(sbu + c * STAGE_STRIDE + OFF_Q, sbu + c * STAGE_STRIDE + OFF_K,
                   qsrc + c * 128, ksrc + c * 128, tid);
        CP_COMMIT();
    }

    float acc[4][4][4];
    #pragma unroll
    for (int a = 0; a < 4; a++)
        #pragma unroll
        for (int b = 0; b < 4; b++)
            #pragma unroll
            for (int c = 0; c < 4; c++) acc[a][b][c] = 0.0f;

    const uint32_t arow_off0 = (warp_m * 64 + (lane & 15)) * 128;
    const uint32_t brow_off = (warp_n * 32 + ((lane >> 4) & 1) * 8 + l7) * 128;
    const uint32_t bksel = (lane >> 3) & 1;

    for (int c = 0; c < NCHUNK; c++) {
        if (c + 1 < NCHUNK) CP_WAIT(1); else CP_WAIT(0);
        __syncthreads();   // chunk c data ready AND stage (c+2)%3 fully consumed

        if (c + 2 < NCHUNK) {
            const int cl = c + 2;
            const uint32_t st = sbu + (uint32_t)(cl % NSTAGE) * STAGE_STRIDE;
            load_stage(st + OFF_Q, st + OFF_K, qsrc + cl * 128, ksrc + cl * 128, tid);
            CP_COMMIT();
        }

        const uint32_t st = sbu + (uint32_t)(c % NSTAGE) * STAGE_STRIDE;
        compute_chunk(st + OFF_Q, st + OFF_K, acc,
                      arow_off0, hb, l7, brow_off, bksel);
    }

    // ---- epilogue: per-row UNNORMALIZED exp sums over this t-half ----
    // Valid logits are bounded (|cos*decay| <= ~1.02) so no max-shift needed;
    // masked lanes give __expf(-1e9) == 0 exactly.
    #pragma unroll
    for (int mf = 0; mf < 4; mf++) {
        #pragma unroll
        for (int h = 0; h < 2; h++) {
            const int row_local = warp_m * 64 + mf * 16 + h * 8 + (int)gid;
            const int s_glob = mtile * 128 + row_local;
            const float qmr = qm_s[row_local];

            float se = 0.0f, sc = 0.0f;
            #pragma unroll
            for (int nf = 0; nf < 4; nf++) {
                #pragma unroll
                for (int dc = 0; dc < 2; dc++) {
                    const int tl = warp_n * 32 + nf * 8 + 2 * (int)tig + dc;
                    const int tg = ntile * 128 + tl;
                    const float v = acc[mf][nf][h * 2 + dc];
                    const float valid = qmr * km_s[tl];
                    int d = s_glob - tg; d = d < 0 ? -d : d;
                    const float lv = v * dtab[d] * valid - (1.0f - valid) * 1e9f;
                    const float e = __expf(lv);
                    se += e;
                    sc = fmaf(e, v, sc);
                }
            }
            #pragma unroll
            for (int o = 1; o <= 2; o <<= 1) {
                se += __shfl_xor_sync(0xffffffffu, se, o);
                sc += __shfl_xor_sync(0xffffffffu, sc, o);
            }
            if (tig == 0) {
                pse[warp_n * 128 + row_local] = se;
                psc[warp_n * 128 + row_local] = sc;
            }
        }
    }
    __syncthreads();

    if (tid < 128) {
        const float S = (pse[tid] + pse[128 + tid]) + (pse[256 + tid] + pse[384 + tid]);
        const float C = (psc[tid] + psc[128 + tid]) + (psc[256 + tid] + psc[384 + tid]);
        const int gidx = (((i * J_DIM + j) * S_DIM) + mtile * 128 + tid) * 2 + ntile;
        g_pse[gidx] = S;
        g_psc[gidx] = C;
    }
}

// --------------- combine t-halves + masked mean; 4 (i,j) per block
__global__ void combine_kernel(const float* __restrict__ q_mask, float* __restrict__ out) {
    __shared__ float sh_s[4][2], sh_q[4][2];
    const int wid = threadIdx.x >> 5, lane = threadIdx.x & 31;
    const int il = wid >> 1;           // local ij 0..3
    const int half = wid & 1;          // s range half
    const int ij = blockIdx.x * 4 + il;
    const int i = ij >> 5;

    float score = 0.0f, qv = 0.0f;
    #pragma unroll
    for (int e = 0; e < 4; e++) {
        const int s = half * 128 + e * 32 + lane;
        const int base = (ij * S_DIM + s) * 2;
        const float S = fmaxf(g_pse[base] + g_pse[base + 1], 1e-30f);
        const float C = g_psc[base] + g_psc[base + 1];
        const float qm = q_mask[i * S_DIM + s];
        score += qm * (C / S);
        qv += qm;
    }
    #pragma unroll
    for (int o = 16; o; o >>= 1) {
        score += __shfl_xor_sync(0xffffffffu, score, o);
        qv    += __shfl_xor_sync(0xffffffffu, qv, o);
    }
    if (lane == 0) { sh_s[il][half] = score; sh_q[il][half] = qv; }
    __syncthreads();
    if (threadIdx.x < 4) {
        const float ts = sh_s[threadIdx.x][0] + sh_s[threadIdx.x][1];
        const float tq = sh_q[threadIdx.x][0] + sh_q[threadIdx.x][1];
        out[blockIdx.x * 4 + threadIdx.x] = ts / fmaxf(tq, 1.0f);
    }
}

// -------------------------------------------------------------------- launch
extern "C" void kernel_launch(void* const* d_in, const int* in_sizes, int n_in,
                              void* d_out, int out_size) {
    const float* q  = (const float*)d_in[0];
    const float* k  = (const float*)d_in[1];
    const float* qm = (const float*)d_in[2];
    const float* km = (const float*)d_in[3];
    const float* ar = (const float*)d_in[4];
    float* out = (float*)d_out;

    norm_kernel<<<(I_DIM + J_DIM) * S_DIM / 16, 256>>>(q, k);

    static int smem_set = 0;
    if (!smem_set) {
        cudaFuncSetAttribute(pair_kernel, cudaFuncAttributeMaxDynamicSharedMemorySize, SMEM_DYN);
        smem_set = 1;
    }
    dim3 grid(4, J_DIM, I_DIM);
    pair_kernel<<<grid, NTH, SMEM_DYN>>>(qm, km, ar);

    combine_kernel<<<I_DIM * J_DIM / 4, 256>>>(qm, out);
}

// round 17
// speedup vs baseline: 1.1053x; 1.1053x over previous
#include <cuda_runtime.h>
#include <cuda_fp16.h>
#include <math.h>
#include <stdint.h>

#define I_DIM 32
#define J_DIM 32
#define S_DIM 256
#define H_DIM 768
#define NTH 256
#define NCHUNK 12          // 768 / 64
#define NSTAGE 3

// smem byte offsets (from 128B-aligned base). Stage = Q 16K + K 16K.
#define STAGE_STRIDE 32768
#define OFF_Q   0
#define OFF_K   16384
#define OFF_DTAB 98304
#define OFF_KM   99328
#define OFF_QM   99840
#define OFF_PSE  100352        // 4 n-warps * 128 rows
#define OFF_PSC  102400
#define SMEM_DYN (104448 + 128)

// ----------------------------------------------------------- device scratch
__device__ __align__(16) __half g_qh[I_DIM * S_DIM * H_DIM];
__device__ __align__(16) __half g_kh[J_DIM * S_DIM * H_DIM];
// per-row unnormalized softmax partials: [(i*32+j)*256 + s_glob]*2 + ntile
__device__ float g_pse[I_DIM * J_DIM * S_DIM * 2];
__device__ float g_psc[I_DIM * J_DIM * S_DIM * 2];

// --------------------------------------------------------------- asm helpers
__device__ __forceinline__ uint32_t smem_u32(const void* p) {
    uint32_t a;
    asm("{ .reg .u64 t; cvta.to.shared.u64 t, %1; cvt.u32.u64 %0, t; }" : "=r"(a) : "l"(p));
    return a;
}
__device__ __forceinline__ void cp16(uint32_t s, const void* g) {
    asm volatile("{ .reg .u64 gg; cvta.to.global.u64 gg, %1; cp.async.cg.shared.global [%0], [gg], 16; }"
                 :: "r"(s), "l"(g));
}
#define CP_COMMIT() asm volatile("cp.async.commit_group;" ::: "memory")
#define CP_WAIT(N)  asm volatile("cp.async.wait_group %0;" :: "n"(N) : "memory")

__device__ __forceinline__ void ldsm4(uint32_t* A, uint32_t addr) {
    asm volatile("ldmatrix.sync.aligned.m8n8.x4.shared.b16 {%0,%1,%2,%3}, [%4];"
                 : "=r"(A[0]), "=r"(A[1]), "=r"(A[2]), "=r"(A[3]) : "r"(addr));
}
__device__ __forceinline__ void mma16816(float* c, const uint32_t* a, uint32_t b0, uint32_t b1) {
    asm volatile("mma.sync.aligned.m16n8k16.row.col.f32.f16.f16.f32 "
                 "{%0,%1,%2,%3}, {%4,%5,%6,%7}, {%8,%9}, {%0,%1,%2,%3};"
                 : "+f"(c[0]), "+f"(c[1]), "+f"(c[2]), "+f"(c[3])
                 : "r"(a[0]), "r"(a[1]), "r"(a[2]), "r"(a[3]), "r"(b0), "r"(b1));
}

// ------------------------------------ normalize -> fp16, one warp per row
__global__ __launch_bounds__(256, 6)
void norm_kernel(const float* __restrict__ q, const float* __restrict__ k) {
    const int row = blockIdx.x * 8 + (threadIdx.x >> 5);
    const int lane = threadIdx.x & 31;
    const int local = (row < I_DIM * S_DIM) ? row : row - I_DIM * S_DIM;
    const float* x = ((row < I_DIM * S_DIM) ? q : k) + (size_t)local * H_DIM;
    __half* hi = ((row < I_DIM * S_DIM) ? g_qh : g_kh) + (size_t)local * H_DIM;

    float4 v[6];
    float s = 0.0f;
    #pragma unroll
    for (int e = 0; e < 6; e++) {
        v[e] = *reinterpret_cast<const float4*>(x + (lane + e * 32) * 4);
        s += v[e].x * v[e].x + v[e].y * v[e].y + v[e].z * v[e].z + v[e].w * v[e].w;
    }
    #pragma unroll
    for (int o = 16; o; o >>= 1) s += __shfl_xor_sync(0xffffffffu, s, o);
    const float iv = 1.0f / fmaxf(sqrtf(s), 1e-12f);

    #pragma unroll
    for (int e = 0; e < 6; e++) {
        __half2 h0 = __floats2half2_rn(v[e].x * iv, v[e].y * iv);
        __half2 h1 = __floats2half2_rn(v[e].z * iv, v[e].w * iv);
        uint2 w;
        w.x = *reinterpret_cast<uint32_t*>(&h0);
        w.y = *reinterpret_cast<uint32_t*>(&h1);
        *reinterpret_cast<uint2*>(hi + (lane + e * 32) * 4) = w;
    }
}

// ----------------------------------------------------------- stage loader
// 128 rows x 64 halves (128B = 8 x 16B groups), swizzle: group ^= row&7.
__device__ __forceinline__ void load_stage(uint32_t qdst, uint32_t kdst,
                                           const char* qsrc, const char* ksrc, int tid) {
    #pragma unroll
    for (int it = 0; it < 4; it++) {               // Q: 128 rows
        const int idx = tid + it * NTH;
        const int row = idx >> 3, g = idx & 7, gs = g ^ (row & 7);
        cp16(qdst + row * 128 + gs * 16, qsrc + (size_t)row * 1536 + g * 16);
    }
    #pragma unroll
    for (int it = 0; it < 4; it++) {               // K: 128 rows
        const int idx = tid + it * NTH;
        const int row = idx >> 3, g = idx & 7, gs = g ^ (row & 7);
        cp16(kdst + row * 128 + gs * 16, ksrc + (size_t)row * 1536 + g * 16);
    }
}

// ----------------------------------------------------------- chunk compute
// Warp tiling: 2 m-warps (64 rows) x 4 n-warps (32 cols). acc[mf(4)][nf(4)][4]
// B fragments double-buffered across ks steps.
__device__ __forceinline__ void compute_chunk(
    uint32_t qs, uint32_t ks_, float acc[4][4][4],
    uint32_t arow_off0, uint32_t hb, uint32_t l7,
    uint32_t brow_off, uint32_t bksel)
{
    uint32_t B[2][2][4];
    {
        const uint32_t bg = (bksel ^ l7) << 4;
        ldsm4(B[0][0], ks_ + brow_off + bg);
        ldsm4(B[0][1], ks_ + brow_off + 2048 + bg);
    }
    #pragma unroll
    for (int ks = 0; ks < 4; ks++) {
        const int cur = ks & 1, nxt = cur ^ 1;
        uint32_t A[4][4];
        const uint32_t agrp = (2u * ks + hb) ^ l7;
        #pragma unroll
        for (int mf = 0; mf < 4; mf++)
            ldsm4(A[mf], qs + arow_off0 + mf * 2048 + (agrp << 4));
        if (ks < 3) {
            const uint32_t bgn = ((2u * (ks + 1) + bksel) ^ l7) << 4;
            ldsm4(B[nxt][0], ks_ + brow_off + bgn);
            ldsm4(B[nxt][1], ks_ + brow_off + 2048 + bgn);
        }
        #pragma unroll
        for (int p = 0; p < 2; p++) {
            #pragma unroll
            for (int half = 0; half < 2; half++) {
                const int nf = 2 * p + half;
                const uint32_t b0 = B[cur][p][half * 2], b1 = B[cur][p][half * 2 + 1];
                mma16816(acc[0][nf], A[0], b0, b1);
                mma16816(acc[1][nf], A[1], b0, b1);
                mma16816(acc[2][nf], A[2], b0, b1);
                mma16816(acc[3][nf], A[3], b0, b1);
            }
        }
    }
}

// ------------------------------------------------ fused pair GEMM + partials
__global__ __launch_bounds__(NTH, 2)
void pair_kernel(const float* __restrict__ q_mask, const float* __restrict__ k_mask,
                 const float* __restrict__ alpha_raw)
{
    extern __shared__ char smraw[];
    const uint32_t rawu = smem_u32(smraw);
    const uint32_t pad = (128u - (rawu & 127u)) & 127u;
    char* sb = smraw + pad;
    const uint32_t sbu = rawu + pad;

    const int mtile = blockIdx.x & 1;
    const int ntile = blockIdx.x >> 1;
    const int j = blockIdx.y;
    const int i = blockIdx.z;
    const int tid = threadIdx.x;
    const int wid = tid >> 5;
    const int lane = tid & 31;
    const int warp_m = wid & 1;        // 2 m-warps (64 s-rows each)
    const int warp_n = wid >> 1;       // 4 n-warps (32 t-cols each)
    const uint32_t gid = lane >> 2, tig = lane & 3;
    const uint32_t hb = lane >> 4, l7 = lane & 7;

    float* dtab = (float*)(sb + OFF_DTAB);
    float* km_s = (float*)(sb + OFF_KM);
    float* qm_s = (float*)(sb + OFF_QM);
    float* pse  = (float*)(sb + OFF_PSE);
    float* psc  = (float*)(sb + OFF_PSC);

    const float araw  = __ldg(alpha_raw);
    const float alpha = fmaxf(araw, 0.0f) + log1pf(expf(-fabsf(araw)));
    dtab[tid] = expf(-alpha * (float)tid);
    if (tid < 128) {
        km_s[tid] = k_mask[j * S_DIM + ntile * 128 + tid];
        qm_s[tid] = q_mask[i * S_DIM + mtile * 128 + tid];
    }

    const char* qsrc = (const char*)(g_qh + ((size_t)i * S_DIM + mtile * 128) * H_DIM);
    const char* ksrc = (const char*)(g_kh + ((size_t)j * S_DIM + ntile * 128) * H_DIM);

    // prologue: chunks 0,1 into stages 0,1
    load_stage(sbu + 0 * STAGE_STRIDE + OFF_Q, sbu + 0 * STAGE_STRIDE + OFF_K,
               qsrc, ksrc, tid);
    CP_COMMIT();
    load_stage(sbu + 1 * STAGE_STRIDE + OFF_Q, sbu + 1 * STAGE_STRIDE + OFF_K,
               qsrc + 128, ksrc + 128, tid);
    CP_COMMIT();

    float acc[4][4][4];
    #pragma unroll
    for (int a = 0; a < 4; a++)
        #pragma unroll
        for (int b = 0; b < 4; b++)
            #pragma unroll
            for (int c = 0; c < 4; c++) acc[a][b][c] = 0.0f;

    const uint32_t arow_off0 = (warp_m * 64 + (lane & 15)) * 128;
    const uint32_t brow_off = (warp_n * 32 + ((lane >> 4) & 1) * 8 + l7) * 128;
    const uint32_t bksel = (lane >> 3) & 1;

    // Fully unrolled chunk loop: all stage addresses compile-time constant,
    // CP_WAIT arms static, ldsm/mma streams pipelinable across chunk seams.
    #pragma unroll
    for (int c = 0; c < NCHUNK; c++) {
        if (c + 1 < NCHUNK) CP_WAIT(1); else CP_WAIT(0);
        __syncthreads();   // chunk c data ready AND stage (c+2)%3 fully consumed

        if (c + 2 < NCHUNK) {
            const int cl = c + 2;
            const uint32_t st = sbu + (uint32_t)(cl % NSTAGE) * STAGE_STRIDE;
            load_stage(st + OFF_Q, st + OFF_K, qsrc + cl * 128, ksrc + cl * 128, tid);
            CP_COMMIT();
        }

        const uint32_t st = sbu + (uint32_t)(c % NSTAGE) * STAGE_STRIDE;
        compute_chunk(st + OFF_Q, st + OFF_K, acc,
                      arow_off0, hb, l7, brow_off, bksel);
    }

    // ---- epilogue: per-row UNNORMALIZED exp sums over this t-half ----
    // Valid logits are bounded (|cos*decay| <= ~1.02) so no max-shift needed;
    // masked lanes give __expf(-1e9) == 0 exactly.
    #pragma unroll
    for (int mf = 0; mf < 4; mf++) {
        #pragma unroll
        for (int h = 0; h < 2; h++) {
            const int row_local = warp_m * 64 + mf * 16 + h * 8 + (int)gid;
            const int s_glob = mtile * 128 + row_local;
            const float qmr = qm_s[row_local];

            float se = 0.0f, sc = 0.0f;
            #pragma unroll
            for (int nf = 0; nf < 4; nf++) {
                #pragma unroll
                for (int dc = 0; dc < 2; dc++) {
                    const int tl = warp_n * 32 + nf * 8 + 2 * (int)tig + dc;
                    const int tg = ntile * 128 + tl;
                    const float v = acc[mf][nf][h * 2 + dc];
                    const float valid = qmr * km_s[tl];
                    int d = s_glob - tg; d = d < 0 ? -d : d;
                    const float lv = v * dtab[d] * valid - (1.0f - valid) * 1e9f;
                    const float e = __expf(lv);
                    se += e;
                    sc = fmaf(e, v, sc);
                }
            }
            #pragma unroll
            for (int o = 1; o <= 2; o <<= 1) {
                se += __shfl_xor_sync(0xffffffffu, se, o);
                sc += __shfl_xor_sync(0xffffffffu, sc, o);
            }
            if (tig == 0) {
                pse[warp_n * 128 + row_local] = se;
                psc[warp_n * 128 + row_local] = sc;
            }
        }
    }
    __syncthreads();

    if (tid < 128) {
        const float S = (pse[tid] + pse[128 + tid]) + (pse[256 + tid] + pse[384 + tid]);
        const float C = (psc[tid] + psc[128 + tid]) + (psc[256 + tid] + psc[384 + tid]);
        const int gidx = (((i * J_DIM + j) * S_DIM) + mtile * 128 + tid) * 2 + ntile;
        g_pse[gidx] = S;
        g_psc[gidx] = C;
    }
}

// --------------- combine t-halves + masked mean; 4 (i,j) per block
__global__ void combine_kernel(const float* __restrict__ q_mask, float* __restrict__ out) {
    __shared__ float sh_s[4][2], sh_q[4][2];
    const int wid = threadIdx.x >> 5, lane = threadIdx.x & 31;
    const int il = wid >> 1;           // local ij 0..3
    const int half = wid & 1;          // s range half
    const int ij = blockIdx.x * 4 + il;
    const int i = ij >> 5;

    float score = 0.0f, qv = 0.0f;
    #pragma unroll
    for (int e = 0; e < 4; e++) {
        const int s = half * 128 + e * 32 + lane;
        const int base = (ij * S_DIM + s) * 2;
        const float S = fmaxf(g_pse[base] + g_pse[base + 1], 1e-30f);
        const float C = g_psc[base] + g_psc[base + 1];
        const float qm = q_mask[i * S_DIM + s];
        score += qm * (C / S);
        qv += qm;
    }
    #pragma unroll
    for (int o = 16; o; o >>= 1) {
        score += __shfl_xor_sync(0xffffffffu, score, o);
        qv    += __shfl_xor_sync(0xffffffffu, qv, o);
    }
    if (lane == 0) { sh_s[il][half] = score; sh_q[il][half] = qv; }
    __syncthreads();
    if (threadIdx.x < 4) {
        const float ts = sh_s[threadIdx.x][0] + sh_s[threadIdx.x][1];
        const float tq = sh_q[threadIdx.x][0] + sh_q[threadIdx.x][1];
        out[blockIdx.x * 4 + threadIdx.x] = ts / fmaxf(tq, 1.0f);
    }
}

// -------------------------------------------------------------------- launch
extern "C" void kernel_launch(void* const* d_in, const int* in_sizes, int n_in,
                              void* d_out, int out_size) {
    const float* q  = (const float*)d_in[0];
    const float* k  = (const float*)d_in[1];
    const float* qm = (const float*)d_in[2];
    const float* km = (const float*)d_in[3];
    const float* ar = (const float*)d_in[4];
    float* out = (float*)d_out;

    norm_kernel<<<(I_DIM + J_DIM) * S_DIM / 8, 256>>>(q, k);

    static int smem_set = 0;
    if (!smem_set) {
        cudaFuncSetAttribute(pair_kernel, cudaFuncAttributeMaxDynamicSharedMemorySize, SMEM_DYN);
        smem_set = 1;
    }
    dim3 grid(4, J_DIM, I_DIM);
    pair_kernel<<<grid, NTH, SMEM_DYN>>>(qm, km, ar);

    combine_kernel<<<I_DIM * J_DIM / 4, 256>>>(qm, out);
}